// round 7
// baseline (speedup 1.0000x reference)
#include <cuda_runtime.h>

#define N_NODES 50000
#define N_EDGES 200000
#define C 32
#define ND 75
#define ED 12
#define NL 3
#define NG 500
#define HID 5
#define BN_EPS 1e-5f

// Scratch (no allocations allowed)
__device__ __align__(128) float g_h[N_NODES * C];        // layer-0 input features
__device__ __align__(128) float g_agg[N_NODES * C];      // conv accumulator
__device__ __align__(128) float g_v[N_NODES * 6 * C];    // v[n,k,d] = sum_c h[n,c] W2[k,c,d]
__device__ __align__(128) float g_coef[NL * N_EDGES * 8];// relu(ea@W1+b1), slot5=1, padded
__device__ float g_stats[2 * C];                         // BN sum / sumsq

// ---- packed fp32x2 helpers (sm_103a) ----
__device__ __forceinline__ void fma2(unsigned long long& acc, unsigned long long a,
                                     unsigned long long b) {
    asm("fma.rn.f32x2 %0, %1, %2, %0;" : "+l"(acc) : "l"(a), "l"(b));
}
__device__ __forceinline__ unsigned long long pack2(float v) {
    unsigned long long r;
    asm("mov.b64 %0, {%1, %1};" : "=l"(r) : "f"(v));
    return r;
}
__device__ __forceinline__ void red_add_v4(float* addr, float4 v) {
    asm volatile("red.global.add.v4.f32 [%0], {%1, %2, %3, %4};"
                 :: "l"(addr), "f"(v.x), "f"(v.y), "f"(v.z), "f"(v.w) : "memory");
}

// ---------------------------------------------------------------------------
// h = leaky(x @ lin_W + lin_b). x rows staged through smem in 3 chunks of 25
// columns (coalesced global reads, conflict-free smem: stride 27).
// ---------------------------------------------------------------------------
__global__ void __launch_bounds__(256) k_init(const float* __restrict__ x,
                                              const float* __restrict__ W,
                                              const float* __restrict__ b) {
    __shared__ __align__(16) float sW[ND * C];   // 9.6 KB
    __shared__ float sb[C];
    __shared__ float sX[256 * 27];               // 27.6 KB (25 cols, stride 27)
    for (int i = threadIdx.x; i < ND * C; i += 256) sW[i] = W[i];
    if (threadIdx.x < C) sb[threadIdx.x] = b[threadIdx.x];

    int nodeBase = blockIdx.x * 256;
    int node = nodeBase + threadIdx.x;

    unsigned long long acc[16];
#pragma unroll
    for (int j = 0; j < 16; j++) acc[j] = 0ULL;

    for (int ch = 0; ch < 3; ch++) {
        __syncthreads();
        // coalesced-ish load of 256 nodes x 25 cols
        for (int i = threadIdx.x; i < 256 * 25; i += 256) {
            int n = i / 25, j = i % 25;
            int gn = nodeBase + n;
            sX[n * 27 + j] = (gn < N_NODES) ? x[(size_t)gn * ND + ch * 25 + j] : 0.f;
        }
        __syncthreads();
        if (node < N_NODES) {
#pragma unroll
            for (int j = 0; j < 25; j++) {
                unsigned long long p = pack2(sX[threadIdx.x * 27 + j]);
                const ulonglong2* wr = (const ulonglong2*)(sW + (ch * 25 + j) * C);
#pragma unroll
                for (int q = 0; q < 8; q++) {
                    ulonglong2 w = wr[q];
                    fma2(acc[2 * q], p, w.x);
                    fma2(acc[2 * q + 1], p, w.y);
                }
            }
        }
    }
    if (node >= N_NODES) return;
    const float* af = (const float*)acc;
    float4* ho = (float4*)(g_h + (size_t)node * C);
#pragma unroll
    for (int q = 0; q < 8; q++) {
        float a0 = af[4 * q] + sb[4 * q];
        float a1 = af[4 * q + 1] + sb[4 * q + 1];
        float a2 = af[4 * q + 2] + sb[4 * q + 2];
        float a3 = af[4 * q + 3] + sb[4 * q + 3];
        float4 v;
        v.x = a0 > 0.f ? a0 : 0.01f * a0;
        v.y = a1 > 0.f ? a1 : 0.01f * a1;
        v.z = a2 > 0.f ? a2 : 0.01f * a2;
        v.w = a3 > 0.f ? a3 : 0.01f * a3;
        ho[q] = v;
    }
}

// ---------------------------------------------------------------------------
// Precompute edge-MLP coefs for ALL layers (edge_attr is layer-invariant).
// ---------------------------------------------------------------------------
__global__ void __launch_bounds__(256) k_coef(const float* __restrict__ ea,
                                              const float* __restrict__ W1,
                                              const float* __restrict__ b1) {
    __shared__ float sW1[NL * ED * HID];
    __shared__ float sb1[NL * HID];
    if (threadIdx.x < NL * ED * HID) sW1[threadIdx.x] = W1[threadIdx.x];
    if (threadIdx.x < NL * HID) sb1[threadIdx.x] = b1[threadIdx.x];
    __syncthreads();
    int e = blockIdx.x * blockDim.x + threadIdx.x;
    if (e >= N_EDGES) return;
    float eav[ED];
    const float4* ear = (const float4*)(ea + (size_t)e * ED);
#pragma unroll
    for (int q = 0; q < 3; q++) {
        float4 v = ear[q];
        eav[4 * q] = v.x; eav[4 * q + 1] = v.y; eav[4 * q + 2] = v.z; eav[4 * q + 3] = v.w;
    }
#pragma unroll
    for (int l = 0; l < NL; l++) {
        float out[8];
#pragma unroll
        for (int k = 0; k < HID; k++) {
            float s = sb1[l * HID + k];
#pragma unroll
            for (int j = 0; j < ED; j++) s += eav[j] * sW1[(l * ED + j) * HID + k];
            out[k] = fmaxf(s, 0.f);
        }
        out[5] = 1.f; out[6] = 0.f; out[7] = 0.f;
        float4* co = (float4*)(g_coef + ((size_t)l * N_EDGES + e) * 8);
        co[0] = make_float4(out[0], out[1], out[2], out[3]);
        co[1] = make_float4(out[4], out[5], out[6], out[7]);
    }
}

// ---------------------------------------------------------------------------
// k_v, smem-tiled: block owns 32 consecutive nodes.
//   A: weights -> smem.  B: coalesced h-tile load (+BN for layers>0) -> padded
//   smem.  C: warps 0-6 compute slots 0-6 (lane = node).  D: coalesced store
//   of contiguous g_v tile (24KB) and agg tile (4KB).
// Dynamic smem: 62464 bytes.
// ---------------------------------------------------------------------------
#define SV_W 0          // 7*1024 floats
#define SV_H 7168       // 32*33
#define SV_V 8224       // 32*193
#define SV_A 14400      // 32*33
#define SV_N 15456      // 4*32 (mu, rs, g, b)
#define SV_CB 15584     // 32
#define SV_TOTAL 15616  // floats (62464 B)

__global__ void __launch_bounds__(256) k_v(const float* __restrict__ W2,
                                           const float* __restrict__ b2,
                                           const float* __restrict__ rootW,
                                           const float* __restrict__ cb,
                                           const float* __restrict__ bng,
                                           const float* __restrict__ bnb,
                                           int first) {
    extern __shared__ float sm[];
    int tid = threadIdx.x;

    // Phase A: weights + norm params
    for (int i = tid; i < HID * C * C; i += 256) sm[SV_W + i] = W2[i];
    for (int i = tid; i < C * C; i += 256) {
        sm[SV_W + 5 * C * C + i] = b2[i];
        sm[SV_W + 6 * C * C + i] = rootW[i];
    }
    if (tid < C) {
        sm[SV_CB + tid] = cb[tid];
        if (!first) {
            float mu = g_stats[tid] * (1.0f / N_NODES);
            float var = g_stats[C + tid] * (1.0f / N_NODES) - mu * mu;
            sm[SV_N + tid] = mu;
            sm[SV_N + C + tid] = rsqrtf(var + BN_EPS);
            sm[SV_N + 2 * C + tid] = bng[tid];
            sm[SV_N + 3 * C + tid] = bnb[tid];
        }
    }
    __syncthreads();

    int nodeBase = blockIdx.x * 32;
    int nv = N_NODES - nodeBase;
    if (nv > 32) nv = 32;

    // Phase B: h tile -> sH (padded stride 33), coalesced float4 global reads
    const float4* gsrc = (const float4*)((first ? g_h : g_agg) + (size_t)nodeBase * C);
    for (int i = tid; i < nv * 8; i += 256) {
        float4 v = gsrc[i];
        int r = i >> 3, c0 = (i & 7) * 4;
        float t[4] = {v.x, v.y, v.z, v.w};
#pragma unroll
        for (int j = 0; j < 4; j++) {
            float val = t[j];
            if (!first) {
                int c = c0 + j;
                val = (val - sm[SV_N + c]) * sm[SV_N + C + c] * sm[SV_N + 2 * C + c] +
                      sm[SV_N + 3 * C + c];
                val = val > 0.f ? val : 0.01f * val;
            }
            sm[SV_H + r * 33 + c0 + j] = val;
        }
    }
    __syncthreads();

    // Phase C: warps 0..6 = slots, lane = node
    int w = tid >> 5, lane = tid & 31;
    if (w < 7 && lane < nv) {
        float h[C];
#pragma unroll
        for (int c = 0; c < C; c++) h[c] = sm[SV_H + lane * 33 + c];
        unsigned long long acc[16];
#pragma unroll
        for (int j = 0; j < 16; j++) acc[j] = 0ULL;
        const float* wbase = sm + SV_W + w * C * C;
#pragma unroll 8
        for (int c = 0; c < C; c++) {
            unsigned long long p = pack2(h[c]);
            const ulonglong2* wr = (const ulonglong2*)(wbase + c * C);
#pragma unroll
            for (int q = 0; q < 8; q++) {
                ulonglong2 ww = wr[q];
                fma2(acc[2 * q], p, ww.x);
                fma2(acc[2 * q + 1], p, ww.y);
            }
        }
        const float* af = (const float*)acc;
        if (w == 6) {
#pragma unroll
            for (int d = 0; d < C; d++)
                sm[SV_A + lane * 33 + d] = af[d] + sm[SV_CB + d];
        } else {
#pragma unroll
            for (int d = 0; d < C; d++)
                sm[SV_V + lane * 193 + w * C + d] = af[d];
        }
    }
    __syncthreads();

    // Phase D: coalesced stores
    float* vout = g_v + (size_t)nodeBase * (6 * C);
    for (int i = tid; i < nv * 192; i += 256) {
        int r = i / 192, j = i - r * 192;
        vout[i] = sm[SV_V + r * 193 + j];
    }
    float* aout = g_agg + (size_t)nodeBase * C;
    for (int i = tid; i < nv * C; i += 256) {
        aout[i] = sm[SV_A + (i >> 5) * 33 + (i & 31)];
    }
}

// ---------------------------------------------------------------------------
// Edge kernel, coalesced: 8 lanes per edge (warp = 4 edges).
// ---------------------------------------------------------------------------
__global__ void __launch_bounds__(256) k_edge(const int* __restrict__ src,
                                              const int* __restrict__ dst,
                                              int layer) {
    if (blockIdx.x == 0 && threadIdx.x < 2 * C) g_stats[threadIdx.x] = 0.f;

    const float* coefL = g_coef + (size_t)layer * N_EDGES * 8;

    int lane = threadIdx.x & 31;
    int warp = (blockIdx.x * blockDim.x + threadIdx.x) >> 5;
    int group = lane >> 3;
    int d4 = lane & 7;
    int e = warp * 4 + group;
    if (e >= N_EDGES) return;

    int sn = __ldg(src + e);
    int dn = __ldg(dst + e);
    const float* cp = coefL + (size_t)e * 8;
    float4 c03 = __ldg((const float4*)cp);
    float2 c45 = __ldg((const float2*)(cp + 4));
    float coef[6] = {c03.x, c03.y, c03.z, c03.w, c45.x, c45.y};

    unsigned long long a0 = 0ULL, a1 = 0ULL;
    const float* vb = g_v + (size_t)sn * (6 * C) + d4 * 4;
#pragma unroll
    for (int k = 0; k < 6; k++) {
        float ck = coef[k];
        if (ck != 0.f) {
            ulonglong2 w = __ldg((const ulonglong2*)(vb + k * C));
            unsigned long long p = pack2(ck);
            fma2(a0, p, w.x);
            fma2(a1, p, w.y);
        }
    }

    float2 lo = *(float2*)&a0, hi = *(float2*)&a1;
    red_add_v4(g_agg + (size_t)dn * C + d4 * 4, make_float4(lo.x, lo.y, hi.x, hi.y));
}

// ---------------------------------------------------------------------------
// BN statistics: per-channel sum / sumsq over g_agg.
// ---------------------------------------------------------------------------
__global__ void __launch_bounds__(256) k_stats() {
    __shared__ float ss[2 * C];
    if (threadIdx.x < 2 * C) ss[threadIdx.x] = 0.f;
    __syncthreads();
    const float4* A = (const float4*)g_agg;
    float4 s = {0.f, 0.f, 0.f, 0.f}, q = {0.f, 0.f, 0.f, 0.f};
    int stride = gridDim.x * blockDim.x;
    for (int i = blockIdx.x * blockDim.x + threadIdx.x; i < N_NODES * 8; i += stride) {
        float4 v = A[i];
        s.x += v.x; s.y += v.y; s.z += v.z; s.w += v.w;
        q.x += v.x * v.x; q.y += v.y * v.y; q.z += v.z * v.z; q.w += v.w * v.w;
    }
#pragma unroll
    for (int off = 8; off <= 16; off <<= 1) {
        s.x += __shfl_xor_sync(0xffffffffu, s.x, off);
        s.y += __shfl_xor_sync(0xffffffffu, s.y, off);
        s.z += __shfl_xor_sync(0xffffffffu, s.z, off);
        s.w += __shfl_xor_sync(0xffffffffu, s.w, off);
        q.x += __shfl_xor_sync(0xffffffffu, q.x, off);
        q.y += __shfl_xor_sync(0xffffffffu, q.y, off);
        q.z += __shfl_xor_sync(0xffffffffu, q.z, off);
        q.w += __shfl_xor_sync(0xffffffffu, q.w, off);
    }
    int lane = threadIdx.x & 31;
    if (lane < 8) {
        int cg = lane * 4;
        atomicAdd(&ss[cg + 0], s.x); atomicAdd(&ss[cg + 1], s.y);
        atomicAdd(&ss[cg + 2], s.z); atomicAdd(&ss[cg + 3], s.w);
        atomicAdd(&ss[C + cg + 0], q.x); atomicAdd(&ss[C + cg + 1], q.y);
        atomicAdd(&ss[C + cg + 2], q.z); atomicAdd(&ss[C + cg + 3], q.w);
    }
    __syncthreads();
    if (threadIdx.x < 2 * C) atomicAdd(&g_stats[threadIdx.x], ss[threadIdx.x]);
}

// ---------------------------------------------------------------------------
// Final: BN (no leaky) + prediction dot + scatter to graphs (batch is sorted).
// ---------------------------------------------------------------------------
__global__ void k_out_init(const float* __restrict__ pb, float* out) {
    int g = blockIdx.x * blockDim.x + threadIdx.x;
    if (g < NG) out[g] = pb[0];
}

__global__ void __launch_bounds__(256) k_fin(const int* __restrict__ batch,
                                             const float* __restrict__ pW,
                                             const float* __restrict__ bng,
                                             const float* __restrict__ bnb,
                                             float* out) {
    __shared__ float snorm[4 * C];
    __shared__ float spw[C];
    if (threadIdx.x < C) {
        float mu = g_stats[threadIdx.x] * (1.0f / N_NODES);
        float var = g_stats[C + threadIdx.x] * (1.0f / N_NODES) - mu * mu;
        snorm[threadIdx.x] = mu;
        snorm[C + threadIdx.x] = rsqrtf(var + BN_EPS);
        snorm[2 * C + threadIdx.x] = bng[threadIdx.x];
        snorm[3 * C + threadIdx.x] = bnb[threadIdx.x];
        spw[threadIdx.x] = pW[threadIdx.x];
    }
    __syncthreads();
    int n = blockIdx.x * blockDim.x + threadIdx.x;
    bool valid = n < N_NODES;
    int nn = valid ? n : N_NODES - 1;
    const float4* ap = (const float4*)(g_agg + (size_t)nn * C);
    float s = 0.f;
#pragma unroll
    for (int q = 0; q < 8; q++) {
        float4 v = ap[q];
        float t[4] = {v.x, v.y, v.z, v.w};
#pragma unroll
        for (int r = 0; r < 4; r++) {
            int c = 4 * q + r;
            float val = (t[r] - snorm[c]) * snorm[C + c] * snorm[2 * C + c] + snorm[3 * C + c];
            s += val * spw[c];
        }
    }
    if (!valid) s = 0.f;
    int bid = batch[nn];
    int bid0 = __shfl_sync(0xffffffffu, bid, 0);
    bool uni = __all_sync(0xffffffffu, bid == bid0 && valid);
    if (uni) {
#pragma unroll
        for (int off = 16; off >= 1; off >>= 1)
            s += __shfl_xor_sync(0xffffffffu, s, off);
        if ((threadIdx.x & 31) == 0) atomicAdd(&out[bid0], s);
    } else if (valid) {
        atomicAdd(&out[bid], s);
    }
}

// ---------------------------------------------------------------------------
extern "C" void kernel_launch(void* const* d_in, const int* in_sizes, int n_in,
                              void* d_out, int out_size) {
    const float* x       = (const float*)d_in[0];
    const int*   ei      = (const int*)d_in[1];
    const float* ea      = (const float*)d_in[2];
    const int*   batch   = (const int*)d_in[3];
    const float* lin_W   = (const float*)d_in[4];
    const float* lin_b   = (const float*)d_in[5];
    const float* mes_W1  = (const float*)d_in[6];
    const float* mes_b1  = (const float*)d_in[7];
    const float* mes_W2  = (const float*)d_in[8];
    const float* mes_b2  = (const float*)d_in[9];
    const float* root_W  = (const float*)d_in[10];
    const float* conv_b  = (const float*)d_in[11];
    const float* bn_g    = (const float*)d_in[12];
    const float* bn_b    = (const float*)d_in[13];
    const float* pred_W  = (const float*)d_in[14];
    const float* pred_b  = (const float*)d_in[15];
    float* out = (float*)d_out;

    const int* src = ei;
    const int* dst = ei + N_EDGES;

    const int vsmem = SV_TOTAL * 4;   // 62464 B
    static int attr_done = 0;
    if (!attr_done) {
        cudaFuncSetAttribute(k_v, cudaFuncAttributeMaxDynamicSharedMemorySize, vsmem);
        attr_done = 1;
    }

    int vblocks = (N_NODES + 31) / 32;               // 1563
    int eblocks = (N_EDGES / 4 * 32 + 255) / 256;    // 8 lanes/edge

    k_init<<<(N_NODES + 255) / 256, 256>>>(x, lin_W, lin_b);
    k_coef<<<(N_EDGES + 255) / 256, 256>>>(ea, mes_W1, mes_b1);
    for (int l = 0; l < NL; l++) {
        k_v<<<vblocks, 256, vsmem>>>(mes_W2 + l * HID * C * C, mes_b2 + l * C * C,
                                     root_W + l * C * C, conv_b + l * C,
                                     l > 0 ? bn_g + (l - 1) * C : bn_g,
                                     l > 0 ? bn_b + (l - 1) * C : bn_b,
                                     l == 0 ? 1 : 0);
        k_edge<<<eblocks, 256>>>(src, dst, l);
        k_stats<<<1184, 256>>>();
    }
    k_out_init<<<2, 256>>>(pred_b, out);
    k_fin<<<(N_NODES + 255) / 256, 256>>>(batch, pred_W, bn_g + 2 * C, bn_b + 2 * C, out);
}

// round 8
// speedup vs baseline: 1.0485x; 1.0485x over previous
#include <cuda_runtime.h>

#define N_NODES 50000
#define N_EDGES 200000
#define C 32
#define ND 75
#define ED 12
#define NL 3
#define NG 500
#define HID 5
#define BN_EPS 1e-5f

// Scratch (no allocations allowed). Ping-pong agg buffers (race-free k_v).
__device__ __align__(128) float g_h[N_NODES * C];         // layer-0 input features
__device__ __align__(128) float g_aggA[N_NODES * C];      // agg buffer A
__device__ __align__(128) float g_aggB[N_NODES * C];      // agg buffer B
__device__ __align__(128) float g_v[N_NODES * 6 * C];     // v[n,k,d]
__device__ __align__(128) float g_coef[NL * N_EDGES * 8]; // edge MLP coefs, padded
__device__ float g_stats[2 * C];                          // BN sum / sumsq

// layer l: k_v input  = l==0 ? g_h : (l==1 ? g_aggA : g_aggB)
//          agg output = l==1 ? g_aggB : g_aggA   (l=0->A, l=1->B, l=2->A)
__device__ __forceinline__ float* agg_out(int layer) {
    return (layer == 1) ? g_aggB : g_aggA;
}

// ---- packed fp32x2 helpers (sm_103a) ----
__device__ __forceinline__ void fma2(unsigned long long& acc, unsigned long long a,
                                     unsigned long long b) {
    asm("fma.rn.f32x2 %0, %1, %2, %0;" : "+l"(acc) : "l"(a), "l"(b));
}
__device__ __forceinline__ unsigned long long pack2(float v) {
    unsigned long long r;
    asm("mov.b64 %0, {%1, %1};" : "=l"(r) : "f"(v));
    return r;
}
__device__ __forceinline__ void red_add_v4(float* addr, float4 v) {
    asm volatile("red.global.add.v4.f32 [%0], {%1, %2, %3, %4};"
                 :: "l"(addr), "f"(v.x), "f"(v.y), "f"(v.z), "f"(v.w) : "memory");
}

// ---------------------------------------------------------------------------
// h = leaky(x @ lin_W + lin_b)   (R6 baseline version)
// ---------------------------------------------------------------------------
__global__ void __launch_bounds__(256) k_init(const float* __restrict__ x,
                                              const float* __restrict__ W,
                                              const float* __restrict__ b) {
    __shared__ __align__(16) float sW[ND * C];
    __shared__ float sb[C];
    for (int i = threadIdx.x; i < ND * C; i += blockDim.x) sW[i] = W[i];
    if (threadIdx.x < C) sb[threadIdx.x] = b[threadIdx.x];
    __syncthreads();
    int n = blockIdx.x * blockDim.x + threadIdx.x;
    if (n >= N_NODES) return;
    float acc[C];
#pragma unroll
    for (int d = 0; d < C; d++) acc[d] = sb[d];
    const float* xr = x + (size_t)n * ND;
#pragma unroll 5
    for (int j = 0; j < ND; j++) {
        float xv = __ldg(xr + j);
#pragma unroll
        for (int d = 0; d < C; d++) acc[d] += xv * sW[j * C + d];
    }
    float4* ho = (float4*)(g_h + (size_t)n * C);
#pragma unroll
    for (int q = 0; q < 8; q++) {
        float4 v;
        float a0 = acc[4 * q], a1 = acc[4 * q + 1], a2 = acc[4 * q + 2], a3 = acc[4 * q + 3];
        v.x = a0 > 0.f ? a0 : 0.01f * a0;
        v.y = a1 > 0.f ? a1 : 0.01f * a1;
        v.z = a2 > 0.f ? a2 : 0.01f * a2;
        v.w = a3 > 0.f ? a3 : 0.01f * a3;
        ho[q] = v;
    }
}

// ---------------------------------------------------------------------------
// Precompute edge-MLP coefs for ALL layers (edge_attr is layer-invariant).
// ---------------------------------------------------------------------------
__global__ void __launch_bounds__(256) k_coef(const float* __restrict__ ea,
                                              const float* __restrict__ W1,
                                              const float* __restrict__ b1) {
    __shared__ float sW1[NL * ED * HID];
    __shared__ float sb1[NL * HID];
    if (threadIdx.x < NL * ED * HID) sW1[threadIdx.x] = W1[threadIdx.x];
    if (threadIdx.x < NL * HID) sb1[threadIdx.x] = b1[threadIdx.x];
    __syncthreads();
    int e = blockIdx.x * blockDim.x + threadIdx.x;
    if (e >= N_EDGES) return;
    float eav[ED];
    const float4* ear = (const float4*)(ea + (size_t)e * ED);
#pragma unroll
    for (int q = 0; q < 3; q++) {
        float4 v = ear[q];
        eav[4 * q] = v.x; eav[4 * q + 1] = v.y; eav[4 * q + 2] = v.z; eav[4 * q + 3] = v.w;
    }
#pragma unroll
    for (int l = 0; l < NL; l++) {
        float out[8];
#pragma unroll
        for (int k = 0; k < HID; k++) {
            float s = sb1[l * HID + k];
#pragma unroll
            for (int j = 0; j < ED; j++) s += eav[j] * sW1[(l * ED + j) * HID + k];
            out[k] = fmaxf(s, 0.f);
        }
        out[5] = 1.f; out[6] = 0.f; out[7] = 0.f;
        float4* co = (float4*)(g_coef + ((size_t)l * N_EDGES + e) * 8);
        co[0] = make_float4(out[0], out[1], out[2], out[3]);
        co[1] = make_float4(out[4], out[5], out[6], out[7]);
    }
}

// ---------------------------------------------------------------------------
// k_v (redesigned): 4 warps per 4-node group.
//   roles 0..2: slot pairs (0,1),(2,3),(4,5) -> g_v   (lane = g*8 + p*4 + q,
//               lane owns 8 cols of slot 2*role+p at col (lane&3)*8)
//   role 3:     slot 6 (rootW) + conv_b      -> agg   (lane = g*8 + q8,
//               lane owns 4 cols at (lane&7)*4)
// h gathered coalesced (1 LDG.128/warp -> 4 lines), broadcast via shfl within
// 8-lane node groups; weights conflict-free LDS (slot stride 1028 floats).
// BN of previous layer applied inline on load. Grid-stride over 12500 groups.
// ---------------------------------------------------------------------------
#define SLOT_STRIDE 1028

__global__ void __launch_bounds__(256) k_v(const float* __restrict__ W2,
                                           const float* __restrict__ b2,
                                           const float* __restrict__ rootW,
                                           const float* __restrict__ cb,
                                           const float* __restrict__ bng,
                                           const float* __restrict__ bnb,
                                           int layer) {
    __shared__ __align__(16) float sW[7 * SLOT_STRIDE + 4];  // ~29 KB
    __shared__ float sA[C], sB[C], sCB[C];
    int tid = threadIdx.x;
    for (int i = tid; i < 5 * C * C; i += 256)
        sW[(i >> 10) * SLOT_STRIDE + (i & 1023)] = W2[i];
    for (int i = tid; i < C * C; i += 256) {
        sW[5 * SLOT_STRIDE + i] = b2[i];
        sW[6 * SLOT_STRIDE + i] = rootW[i];
    }
    if (tid < C) {
        sCB[tid] = cb[tid];
        if (layer > 0) {
            float mu = g_stats[tid] * (1.0f / N_NODES);
            float var = g_stats[C + tid] * (1.0f / N_NODES) - mu * mu;
            float Av = rsqrtf(var + BN_EPS) * bng[tid];
            sA[tid] = Av;
            sB[tid] = bnb[tid] - mu * Av;
        }
    }
    __syncthreads();

    int w = tid >> 5, lane = tid & 31;
    int role = w & 3;
    int ch = lane & 7;                       // h float4-chunk owned by this lane
    int g = lane >> 3;                       // node within 4-node group
    int colBase = (role < 3) ? (lane & 3) * 8 : (lane & 7) * 4;
    int slotL = (role < 3) ? 2 * role + ((lane >> 2) & 1) : 6;
    const float* wb = sW + slotL * SLOT_STRIDE + colBase;

    // per-lane norm / bias params (constant across nodes)
    float nA[4], nB[4], cb4[4];
    if (layer > 0) {
#pragma unroll
        for (int j = 0; j < 4; j++) { nA[j] = sA[ch * 4 + j]; nB[j] = sB[ch * 4 + j]; }
    }
    if (role == 3) {
#pragma unroll
        for (int j = 0; j < 4; j++) cb4[j] = sCB[(lane & 7) * 4 + j];
    }

    const float* hin = (layer == 0) ? g_h : (layer == 1 ? g_aggA : g_aggB);
    float* aout = agg_out(layer);

    for (int grp = blockIdx.x * 2 + (w >> 2); grp < N_NODES / 4; grp += gridDim.x * 2) {
        int node = grp * 4 + g;
        float4 hv = ((const float4*)(hin + (size_t)node * C))[ch];
        if (layer > 0) {
            hv.x = hv.x * nA[0] + nB[0]; hv.x = hv.x > 0.f ? hv.x : 0.01f * hv.x;
            hv.y = hv.y * nA[1] + nB[1]; hv.y = hv.y > 0.f ? hv.y : 0.01f * hv.y;
            hv.z = hv.z * nA[2] + nB[2]; hv.z = hv.z > 0.f ? hv.z : 0.01f * hv.z;
            hv.w = hv.w * nA[3] + nB[3]; hv.w = hv.w > 0.f ? hv.w : 0.01f * hv.w;
        }

        if (role < 3) {
            unsigned long long a0 = 0, a1 = 0, a2 = 0, a3 = 0;
#pragma unroll
            for (int c = 0; c < 32; c++) {
                int src = (lane & 24) | (c >> 2);
                float hc;
                if ((c & 3) == 0)      hc = __shfl_sync(0xffffffffu, hv.x, src);
                else if ((c & 3) == 1) hc = __shfl_sync(0xffffffffu, hv.y, src);
                else if ((c & 3) == 2) hc = __shfl_sync(0xffffffffu, hv.z, src);
                else                   hc = __shfl_sync(0xffffffffu, hv.w, src);
                unsigned long long p = pack2(hc);
                const ulonglong2* wr = (const ulonglong2*)(wb + c * C);
                ulonglong2 w0 = wr[0], w1 = wr[1];
                fma2(a0, p, w0.x); fma2(a1, p, w0.y);
                fma2(a2, p, w1.x); fma2(a3, p, w1.y);
            }
            float* vo = g_v + (size_t)node * 192 + slotL * C + colBase;
            float2 l0 = *(float2*)&a0, l1 = *(float2*)&a1;
            float2 l2 = *(float2*)&a2, l3 = *(float2*)&a3;
            ((float4*)vo)[0] = make_float4(l0.x, l0.y, l1.x, l1.y);
            ((float4*)vo)[1] = make_float4(l2.x, l2.y, l3.x, l3.y);
        } else {
            unsigned long long a0 = 0, a1 = 0;
#pragma unroll
            for (int c = 0; c < 32; c++) {
                int src = (lane & 24) | (c >> 2);
                float hc;
                if ((c & 3) == 0)      hc = __shfl_sync(0xffffffffu, hv.x, src);
                else if ((c & 3) == 1) hc = __shfl_sync(0xffffffffu, hv.y, src);
                else if ((c & 3) == 2) hc = __shfl_sync(0xffffffffu, hv.z, src);
                else                   hc = __shfl_sync(0xffffffffu, hv.w, src);
                unsigned long long p = pack2(hc);
                ulonglong2 w0 = *(const ulonglong2*)(wb + c * C);
                fma2(a0, p, w0.x); fma2(a1, p, w0.y);
            }
            float2 lo = *(float2*)&a0, hi = *(float2*)&a1;
            *(float4*)(aout + (size_t)node * C + colBase) =
                make_float4(lo.x + cb4[0], lo.y + cb4[1], hi.x + cb4[2], hi.y + cb4[3]);
        }
    }
}

// ---------------------------------------------------------------------------
// Edge kernel, coalesced: 8 lanes per edge (warp = 4 edges).
// ---------------------------------------------------------------------------
__global__ void __launch_bounds__(256) k_edge(const int* __restrict__ src,
                                              const int* __restrict__ dst,
                                              int layer) {
    if (blockIdx.x == 0 && threadIdx.x < 2 * C) g_stats[threadIdx.x] = 0.f;

    const float* coefL = g_coef + (size_t)layer * N_EDGES * 8;
    float* aout = agg_out(layer);

    int lane = threadIdx.x & 31;
    int warp = (blockIdx.x * blockDim.x + threadIdx.x) >> 5;
    int group = lane >> 3;
    int d4 = lane & 7;
    int e = warp * 4 + group;
    if (e >= N_EDGES) return;

    int sn = __ldg(src + e);
    int dn = __ldg(dst + e);
    const float* cp = coefL + (size_t)e * 8;
    float4 c03 = __ldg((const float4*)cp);
    float2 c45 = __ldg((const float2*)(cp + 4));
    float coef[6] = {c03.x, c03.y, c03.z, c03.w, c45.x, c45.y};

    unsigned long long a0 = 0ULL, a1 = 0ULL;
    const float* vb = g_v + (size_t)sn * (6 * C) + d4 * 4;
#pragma unroll
    for (int k = 0; k < 6; k++) {
        float ck = coef[k];
        if (ck != 0.f) {
            ulonglong2 w = __ldg((const ulonglong2*)(vb + k * C));
            unsigned long long p = pack2(ck);
            fma2(a0, p, w.x);
            fma2(a1, p, w.y);
        }
    }

    float2 lo = *(float2*)&a0, hi = *(float2*)&a1;
    red_add_v4(aout + (size_t)dn * C + d4 * 4, make_float4(lo.x, lo.y, hi.x, hi.y));
}

// ---------------------------------------------------------------------------
// BN statistics: per-channel sum / sumsq over this layer's agg buffer.
// ---------------------------------------------------------------------------
__global__ void __launch_bounds__(256) k_stats(int layer) {
    __shared__ float ss[2 * C];
    if (threadIdx.x < 2 * C) ss[threadIdx.x] = 0.f;
    __syncthreads();
    const float4* A = (const float4*)agg_out(layer);
    float4 s = {0.f, 0.f, 0.f, 0.f}, q = {0.f, 0.f, 0.f, 0.f};
    int stride = gridDim.x * blockDim.x;
    for (int i = blockIdx.x * blockDim.x + threadIdx.x; i < N_NODES * 8; i += stride) {
        float4 v = A[i];
        s.x += v.x; s.y += v.y; s.z += v.z; s.w += v.w;
        q.x += v.x * v.x; q.y += v.y * v.y; q.z += v.z * v.z; q.w += v.w * v.w;
    }
#pragma unroll
    for (int off = 8; off <= 16; off <<= 1) {
        s.x += __shfl_xor_sync(0xffffffffu, s.x, off);
        s.y += __shfl_xor_sync(0xffffffffu, s.y, off);
        s.z += __shfl_xor_sync(0xffffffffu, s.z, off);
        s.w += __shfl_xor_sync(0xffffffffu, s.w, off);
        q.x += __shfl_xor_sync(0xffffffffu, q.x, off);
        q.y += __shfl_xor_sync(0xffffffffu, q.y, off);
        q.z += __shfl_xor_sync(0xffffffffu, q.z, off);
        q.w += __shfl_xor_sync(0xffffffffu, q.w, off);
    }
    int lane = threadIdx.x & 31;
    if (lane < 8) {
        int cg = lane * 4;
        atomicAdd(&ss[cg + 0], s.x); atomicAdd(&ss[cg + 1], s.y);
        atomicAdd(&ss[cg + 2], s.z); atomicAdd(&ss[cg + 3], s.w);
        atomicAdd(&ss[C + cg + 0], q.x); atomicAdd(&ss[C + cg + 1], q.y);
        atomicAdd(&ss[C + cg + 2], q.z); atomicAdd(&ss[C + cg + 3], q.w);
    }
    __syncthreads();
    if (threadIdx.x < 2 * C) atomicAdd(&g_stats[threadIdx.x], ss[threadIdx.x]);
}

// ---------------------------------------------------------------------------
// Final: BN (no leaky) + prediction dot + scatter to graphs (batch is sorted).
// Layer-2 agg lives in g_aggA. Tail lanes clamp and contribute 0.
// ---------------------------------------------------------------------------
__global__ void k_out_init(const float* __restrict__ pb, float* out) {
    int g = blockIdx.x * blockDim.x + threadIdx.x;
    if (g < NG) out[g] = pb[0];
}

__global__ void __launch_bounds__(256) k_fin(const int* __restrict__ batch,
                                             const float* __restrict__ pW,
                                             const float* __restrict__ bng,
                                             const float* __restrict__ bnb,
                                             float* out) {
    __shared__ float snorm[4 * C];
    __shared__ float spw[C];
    if (threadIdx.x < C) {
        float mu = g_stats[threadIdx.x] * (1.0f / N_NODES);
        float var = g_stats[C + threadIdx.x] * (1.0f / N_NODES) - mu * mu;
        snorm[threadIdx.x] = mu;
        snorm[C + threadIdx.x] = rsqrtf(var + BN_EPS);
        snorm[2 * C + threadIdx.x] = bng[threadIdx.x];
        snorm[3 * C + threadIdx.x] = bnb[threadIdx.x];
        spw[threadIdx.x] = pW[threadIdx.x];
    }
    __syncthreads();
    int n = blockIdx.x * blockDim.x + threadIdx.x;
    bool valid = n < N_NODES;
    int nn = valid ? n : N_NODES - 1;
    const float4* ap = (const float4*)(g_aggA + (size_t)nn * C);
    float s = 0.f;
#pragma unroll
    for (int q = 0; q < 8; q++) {
        float4 v = ap[q];
        float t[4] = {v.x, v.y, v.z, v.w};
#pragma unroll
        for (int r = 0; r < 4; r++) {
            int c = 4 * q + r;
            float val = (t[r] - snorm[c]) * snorm[C + c] * snorm[2 * C + c] + snorm[3 * C + c];
            s += val * spw[c];
        }
    }
    if (!valid) s = 0.f;
    int bid = batch[nn];
    int bid0 = __shfl_sync(0xffffffffu, bid, 0);
    bool uni = __all_sync(0xffffffffu, bid == bid0 && valid);
    if (uni) {
#pragma unroll
        for (int off = 16; off >= 1; off >>= 1)
            s += __shfl_xor_sync(0xffffffffu, s, off);
        if ((threadIdx.x & 31) == 0) atomicAdd(&out[bid0], s);
    } else if (valid) {
        atomicAdd(&out[bid], s);
    }
}

// ---------------------------------------------------------------------------
extern "C" void kernel_launch(void* const* d_in, const int* in_sizes, int n_in,
                              void* d_out, int out_size) {
    const float* x       = (const float*)d_in[0];
    const int*   ei      = (const int*)d_in[1];
    const float* ea      = (const float*)d_in[2];
    const int*   batch   = (const int*)d_in[3];
    const float* lin_W   = (const float*)d_in[4];
    const float* lin_b   = (const float*)d_in[5];
    const float* mes_W1  = (const float*)d_in[6];
    const float* mes_b1  = (const float*)d_in[7];
    const float* mes_W2  = (const float*)d_in[8];
    const float* mes_b2  = (const float*)d_in[9];
    const float* root_W  = (const float*)d_in[10];
    const float* conv_b  = (const float*)d_in[11];
    const float* bn_g    = (const float*)d_in[12];
    const float* bn_b    = (const float*)d_in[13];
    const float* pred_W  = (const float*)d_in[14];
    const float* pred_b  = (const float*)d_in[15];
    float* out = (float*)d_out;

    const int* src = ei;
    const int* dst = ei + N_EDGES;

    int eblocks = (N_EDGES / 4 * 32 + 255) / 256;    // 8 lanes/edge

    k_init<<<(N_NODES + 255) / 256, 256>>>(x, lin_W, lin_b);
    k_coef<<<(N_EDGES + 255) / 256, 256>>>(ea, mes_W1, mes_b1);
    for (int l = 0; l < NL; l++) {
        k_v<<<592, 256>>>(mes_W2 + l * HID * C * C, mes_b2 + l * C * C,
                          root_W + l * C * C, conv_b + l * C,
                          l > 0 ? bn_g + (l - 1) * C : bn_g,
                          l > 0 ? bn_b + (l - 1) * C : bn_b, l);
        k_edge<<<eblocks, 256>>>(src, dst, l);
        k_stats<<<1184, 256>>>(l);
    }
    k_out_init<<<2, 256>>>(pred_b, out);
    k_fin<<<(N_NODES + 255) / 256, 256>>>(batch, pred_W, bn_g + 2 * C, bn_b + 2 * C, out);
}